// round 17
// baseline (speedup 1.0000x reference)
#include <cuda_runtime.h>
#include <cuda_fp16.h>
#include <cstdint>

#define NEDGES 65536
#define NNODES 50000
#define NPAD   50048          // 391 * 128
#define DNODE  1024
#define DHID   1024

// ---------------------------------------------------------------------------
// Device scratch (static). Referenced ONLY from device code — passing a
// __device__ array as a kernel argument from host passes the host shadow
// address (GB300/ATS silently writes host memory!).
// ---------------------------------------------------------------------------
__device__ __half g_nf[(size_t)NNODES * DNODE];                 // fp16
__device__ __half g_W1T[(size_t)(2 * DNODE) * DHID];            // [N'=2048][K=1024]
__device__ __half g_W2T[(size_t)DHID * DHID];                   // [N=1024][K=1024]
__device__ __half g_P[(size_t)NPAD * (2 * DNODE)];              // U|V  fp16 [NPAD][2048]
__device__ __half g_H[(size_t)NEDGES * DHID];                   // fp16

__device__ __forceinline__ uint32_t smem_u32(const void* p) {
    uint32_t a;
    asm("{ .reg .u64 t; cvta.to.shared.u64 t, %1; cvt.u32.u64 %0, t; }" : "=r"(a) : "l"(p));
    return a;
}
__device__ __forceinline__ void cp16(uint32_t saddr, const void* g) {
    asm volatile("cp.async.cg.shared.global [%0], [%1], 16;" :: "r"(saddr), "l"(g));
}
__device__ __forceinline__ void cp_commit() {
    asm volatile("cp.async.commit_group;");
}
template<int N>
__device__ __forceinline__ void cp_wait() {
    asm volatile("cp.async.wait_group %0;" :: "n"(N));
}
__device__ __forceinline__ void ldsm4(uint32_t* r, uint32_t addr) {
    asm volatile("ldmatrix.sync.aligned.m8n8.x4.shared.b16 {%0,%1,%2,%3}, [%4];"
                 : "=r"(r[0]), "=r"(r[1]), "=r"(r[2]), "=r"(r[3]) : "r"(addr));
}
__device__ __forceinline__ void mma16816(float* c, const uint32_t* a,
                                         uint32_t b0, uint32_t b1) {
    asm volatile(
        "mma.sync.aligned.m16n8k16.row.col.f32.f16.f16.f32 "
        "{%0,%1,%2,%3}, {%4,%5,%6,%7}, {%8,%9}, {%0,%1,%2,%3};"
        : "+f"(c[0]), "+f"(c[1]), "+f"(c[2]), "+f"(c[3])
        : "r"(a[0]), "r"(a[1]), "r"(a[2]), "r"(a[3]), "r"(b0), "r"(b1));
}

// ---------------------------------------------------------------------------
// Pre-pass kernels (globals written device-side)
// ---------------------------------------------------------------------------
__global__ void conv_nf_kernel(const float4* __restrict__ in, int n4)
{
    int id = blockIdx.x * blockDim.x + threadIdx.x;
    if (id >= n4) return;
    float4 v = in[id];
    __half2 p0 = __floats2half2_rn(v.x, v.y);
    __half2 p1 = __floats2half2_rn(v.z, v.w);
    *reinterpret_cast<uint2*>(g_nf + 4 * (size_t)id) =
        make_uint2(*reinterpret_cast<uint32_t*>(&p0), *reinterpret_cast<uint32_t*>(&p1));
}

// W1 [2048,1024] -> B' [n'=2048][k=1024] fp16:
//   n'<1024:  B'[n',k] = W1[k,      n']        (U = nf @ W1_top)
//   n'>=1024: B'[n',k] = W1[k+1024, n'-1024]   (V = nf @ W1_bot)
__global__ void transpose_W1(const float* __restrict__ W1)
{
    size_t id = (size_t)blockIdx.x * blockDim.x + threadIdx.x;
    if (id >= (size_t)(2 * DNODE) * DHID) return;
    int n = (int)(id >> 10);          // 0..2047
    int k = (int)(id & 1023);
    int srow = (n < DHID) ? k : (k + DNODE);
    int scol = n & (DHID - 1);
    g_W1T[id] = __float2half_rn(W1[(size_t)srow * DHID + scol]);
}

// W2 [1024,1024] -> W2T [N][K] fp16
__global__ void transpose_W2(const float* __restrict__ W2)
{
    size_t id = (size_t)blockIdx.x * blockDim.x + threadIdx.x;
    if (id >= (size_t)DHID * DHID) return;
    int k = (int)(id & 1023);
    int n = (int)(id >> 10);
    g_W2T[id] = __float2half_rn(W2[(size_t)k * DHID + n]);
}

// Combine: H[e,:] = relu(U[src[e],:] + V[dst[e],:] + b1) -> fp16 g_H.
__global__ __launch_bounds__(256)
void combine_kernel(const int* __restrict__ src, const int* __restrict__ dst,
                    const float* __restrict__ b1)
{
    const int e = blockIdx.x;
    const int t = threadIdx.x;
    const int s = src[e], d = dst[e];
    const uint2 uu = *reinterpret_cast<const uint2*>(g_P + (size_t)s * 2048 + t * 4);
    const uint2 vv = *reinterpret_cast<const uint2*>(g_P + (size_t)d * 2048 + 1024 + t * 4);
    const float4 bb = reinterpret_cast<const float4*>(b1)[t];
    float2 u0 = __half22float2(*reinterpret_cast<const __half2*>(&uu.x));
    float2 u1 = __half22float2(*reinterpret_cast<const __half2*>(&uu.y));
    float2 v0 = __half22float2(*reinterpret_cast<const __half2*>(&vv.x));
    float2 v1 = __half22float2(*reinterpret_cast<const __half2*>(&vv.y));
    float w0 = u0.x + v0.x + bb.x, w1 = u0.y + v0.y + bb.y;
    float w2 = u1.x + v1.x + bb.z, w3 = u1.y + v1.y + bb.w;
    w0 = w0 > 0.0f ? w0 : 0.0f;  w1 = w1 > 0.0f ? w1 : 0.0f;
    w2 = w2 > 0.0f ? w2 : 0.0f;  w3 = w3 > 0.0f ? w3 : 0.0f;
    __half2 p0 = __floats2half2_rn(w0, w1);
    __half2 p1 = __floats2half2_rn(w2, w3);
    *reinterpret_cast<uint2*>(g_H + ((size_t)e << 10) + t * 4) =
        make_uint2(*reinterpret_cast<uint32_t*>(&p0), *reinterpret_cast<uint32_t*>(&p1));
}

// ---------------------------------------------------------------------------
// Pure fp16 raw-MMA GEMM: D = A * B, fp32 accumulate.
//   BM=128, BN=128, BK=64; 8 warps (4m x 2n), warp tile 32x64.
//   Fragment double-buffering: ldsm(kk+1) issued BEFORE the mmas of kk,
//   so smem-crossbar traffic overlaps tensor time (was phase-serialized).
//   cp.async double-buffered, ONE barrier per 64-wide k-tile (16 total).
//   MODE 0 (node): A = g_nf rows (clamped), out = g_P fp16 (stride 2048).
//   MODE 1 (stage2): A = g_H rows, out = param fp32 (stride 1024) + bias.
// ---------------------------------------------------------------------------
static constexpr int RSB  = 144;                // 64 fp16 = 128B + 16B pad
static constexpr int MBUF = 128 * RSB;          // 18432 B: one matrix buffer
static constexpr int SBUF = 2 * MBUF;           // 36864 B: A|B
static constexpr int HDR  = 1024;               // s_bias
static constexpr int SMEM_BYTES = HDR + 2 * SBUF;   // 74752

template<int MODE>
__global__ __launch_bounds__(256, 2)
void gemm_kernel(const float* __restrict__ bias, float* __restrict__ out)
{
    extern __shared__ char smem[];
    float* s_bias = (float*)smem;
    char*  tiles  = smem + HDR;
    const uint32_t tiles_u32 = smem_u32(tiles);

    const int tid  = threadIdx.x;
    const int lane = tid & 31;
    const int wid  = tid >> 5;
    const int wm   = wid & 3;      // 4 warps along M (32 rows each)
    const int wn   = wid >> 2;     // 2 warps along N (64 cols each)
    const int m0 = blockIdx.y * 128;
    const int n0 = blockIdx.x * 128;

    if (MODE == 1 && tid < 128) s_bias[tid] = bias[n0 + tid];
    __syncthreads();

    const __half* A = (MODE == 0) ? g_nf : g_H;
    const __half* B = (MODE == 0) ? g_W1T : g_W2T;

    constexpr int NT = 16;   // K = 1024, BK = 64

    float acc[2][8][4];
    #pragma unroll
    for (int i = 0; i < 2; ++i)
        #pragma unroll
        for (int j = 0; j < 8; ++j)
            #pragma unroll
            for (int q = 0; q < 4; ++q) acc[i][j][q] = 0.0f;

    const int lrow = lane & 15;
    const int lkb  = (lane >> 4) * 16;
    const uint32_t aBase = tiles_u32 + (wm * 32 + lrow) * RSB + lkb;
    const uint32_t bBase = tiles_u32 + MBUF + (wn * 64 + lrow) * RSB + lkb;

    // A row index for loads (clamped for the padded node tail)
    const int arow_l = tid >> 1;
    int arow_g = m0 + arow_l;
    if (MODE == 0 && arow_g >= NNODES) arow_g = 0;   // padding rows: load row 0

    // 64 fp16 per row per tile: thread t -> row t/2, 64B half (t&1), 4 chunks
    auto issue_tile = [&](int kt, int s) {
        const int kglob = kt * 64;
        const int half = (tid & 1) * 32;   // fp16 elem offset of the 64B half
        const uint32_t base = tiles_u32 + s * SBUF + arow_l * RSB + half * 2;
        const size_t gA = ((size_t)arow_g << 10) + kglob + half;
        const size_t gB = (size_t)(n0 + arow_l) * 1024 + kglob + half;
        #pragma unroll
        for (int ch = 0; ch < 4; ++ch) {
            cp16(base + 0 * MBUF + ch * 16, A + gA + ch * 8);
            cp16(base + 1 * MBUF + ch * 16, B + gB + ch * 8);
        }
    };

    auto compute = [&](int s) {
        const uint32_t aB = aBase + s * SBUF;
        const uint32_t bB = bBase + s * SBUF;
        uint32_t ah[2][2][4], b[2][4][4];   // [pipeline buf][...]
        // prologue: fragments for kk = 0
        ldsm4(ah[0][0], aB);
        ldsm4(ah[0][1], aB + 16 * RSB);
        #pragma unroll
        for (int j = 0; j < 4; ++j)
            ldsm4(b[0][j], bB + j * 16 * RSB);
        #pragma unroll
        for (int kk = 0; kk < 4; ++kk) {
            const int cur = kk & 1, nxt = cur ^ 1;
            if (kk < 3) {
                // prefetch kk+1 fragments BEFORE the mmas of kk:
                // crossbar traffic overlaps tensor-pipe time
                const uint32_t cb = (kk + 1) * 32;
                ldsm4(ah[nxt][0], aB + cb);
                ldsm4(ah[nxt][1], aB + 16 * RSB + cb);
                #pragma unroll
                for (int j = 0; j < 4; ++j)
                    ldsm4(b[nxt][j], bB + j * 16 * RSB + cb);
            }
            #pragma unroll
            for (int mi = 0; mi < 2; ++mi)
                #pragma unroll
                for (int j = 0; j < 4; ++j)
                    #pragma unroll
                    for (int s2 = 0; s2 < 2; ++s2)
                        mma16816(acc[mi][j * 2 + s2], ah[cur][mi],
                                 b[cur][j][s2], b[cur][j][s2 + 2]);
        }
    };

    issue_tile(0, 0);
    cp_commit();
    for (int kt = 0; kt < NT; ++kt) {
        cp_wait<0>();
        __syncthreads();
        if (kt + 1 < NT) {
            issue_tile(kt + 1, (kt + 1) & 1);
            cp_commit();
        }
        compute(kt & 1);
    }

    // ---- direct register epilogue ----
    const int grp = lane >> 2, tg = lane & 3;
    #pragma unroll
    for (int mi = 0; mi < 2; ++mi) {
        const int rbase = m0 + wm * 32 + mi * 16 + grp;
        #pragma unroll
        for (int n8 = 0; n8 < 8; ++n8) {
            const float* c = acc[mi][n8];
            const int colL = wn * 64 + n8 * 8 + tg * 2;
            const int col  = n0 + colL;
            #pragma unroll
            for (int half = 0; half < 2; ++half) {
                const int r = rbase + half * 8;
                if (MODE == 0) {
                    // P fp16, row stride 2048 (skip padded rows)
                    if (r < NNODES) {
                        __half2 p = __floats2half2_rn(c[half * 2 + 0], c[half * 2 + 1]);
                        *reinterpret_cast<uint32_t*>(g_P + (size_t)r * 2048 + col) =
                            *reinterpret_cast<uint32_t*>(&p);
                    }
                } else {
                    const float b0 = s_bias[colL], b1v = s_bias[colL + 1];
                    *reinterpret_cast<float2*>(out + ((size_t)r << 10) + col) =
                        make_float2(c[half * 2 + 0] + b0, c[half * 2 + 1] + b1v);
                }
            }
        }
    }
}

// ---------------------------------------------------------------------------
extern "C" void kernel_launch(void* const* d_in, const int* in_sizes, int n_in,
                              void* d_out, int out_size)
{
    const float* nf  = (const float*)d_in[0];
    const int*   src = (const int*)d_in[1];   // JAX int64 downcasts to int32 (x64 off)
    const int*   dst = (const int*)d_in[2];
    const float* W1  = (const float*)d_in[3];
    const float* b1  = (const float*)d_in[4];
    const float* W2  = (const float*)d_in[5];
    const float* b2  = (const float*)d_in[6];
    float*       out = (float*)d_out;

    cudaFuncSetAttribute(gemm_kernel<0>,
                         cudaFuncAttributeMaxDynamicSharedMemorySize, SMEM_BYTES);
    cudaFuncSetAttribute(gemm_kernel<1>,
                         cudaFuncAttributeMaxDynamicSharedMemorySize, SMEM_BYTES);

    // 1) convert node features to fp16
    {
        int n4 = (NNODES * DNODE) / 4;
        conv_nf_kernel<<<(n4 + 255) / 256, 256>>>((const float4*)nf, n4);
    }
    // 2) transpose weights to fp16 [N][K]
    {
        size_t t1 = (size_t)(2 * DNODE) * DHID;
        transpose_W1<<<(unsigned)((t1 + 255) / 256), 256>>>(W1);
        size_t t2 = (size_t)DHID * DHID;
        transpose_W2<<<(unsigned)((t2 + 255) / 256), 256>>>(W2);
    }
    // 3) node GEMM: P = nf @ [W1_top | W1_bot]   (M=50048, N=2048, K=1024)
    {
        dim3 grid(2 * DNODE / 128, NPAD / 128);   // (16, 391)
        gemm_kernel<0><<<grid, 256, SMEM_BYTES>>>(nullptr, nullptr);
    }
    // 4) combine: H = relu(U[src] + V[dst] + b1) -> fp16 g_H
    {
        combine_kernel<<<NEDGES, 256>>>(src, dst, b1);
    }
    // 5) stage 2: out = H @ W2 + b2   (M=65536, N=1024, K=1024)
    {
        dim3 grid(DHID / 128, NEDGES / 128);      // (8, 512)
        gemm_kernel<1><<<grid, 256, SMEM_BYTES>>>(b2, out);
    }
}